// round 1
// baseline (speedup 1.0000x reference)
#include <cuda_runtime.h>
#include <cuda_bf16.h>
#include <cstdint>

// ---------------- problem constants ----------------
#define BATCH 2
#define DIM   128
#define HGT   128
#define WID   128
#define HW    (HGT*WID)        // 16384
#define HEADS 4
#define CH    32               // channels per head
#define OC1   384
#define IC1   128
#define OC2   384
#define IC2   384
#define OC3   128
#define IC3   128

// ---------------- device scratch (no allocations allowed) ----------------
__device__ float g_w1[OC1*IC1];          // 384x128
__device__ float g_w2[OC2*IC2*9];        // 384x384x9  (5.3 MB)
__device__ float g_w3[OC3*IC3];          // 128x128
__device__ float g_y1[BATCH*OC1*HW];     // 50.3 MB
__device__ float g_y2[BATCH*OC2*HW];     // 50.3 MB
__device__ float g_invn[BATCH*256];      // inv norms for q(128) + k(128) channels
__device__ float g_part[8*32*32*32];     // bh, split, c, d partial dots
__device__ float g_attn[8*32*32];        // softmaxed attention
__device__ float g_o[BATCH*DIM*HW];      // attention output (pre-projection)

// ---------------- quaternion weight expansion ----------------
// Hamilton block matrix:
// row r: [ r, -i, -j, -k]
// row i: [ i,  r, -k,  j]
// row j: [ j,  k,  r, -i]
// row k: [ k, -j,  i,  r]
__constant__ int   c_comp[16] = {0,1,2,3, 1,0,3,2, 2,3,0,1, 3,2,1,0};
__constant__ float c_sign[16] = {1,-1,-1,-1, 1,1,-1,1, 1,1,1,-1, 1,-1,1,1};

__global__ void expand_kernel(const float* __restrict__ r, const float* __restrict__ i,
                              const float* __restrict__ j, const float* __restrict__ k,
                              float* __restrict__ W, int Co, int Ci, int taps, int total) {
    int idx = blockIdx.x * blockDim.x + threadIdx.x;
    if (idx >= total) return;
    int IC = 4 * Ci;
    int t    = idx % taps;
    int rest = idx / taps;
    int ic = rest % IC;
    int oc = rest / IC;
    int br = oc / Co, o  = oc % Co;
    int bc = ic / Ci, ci = ic % Ci;
    const float* comps[4] = {r, i, j, k};
    W[idx] = c_sign[br*4+bc] * comps[c_comp[br*4+bc]][(o*Ci + ci)*taps + t];
}

// ---------------- generic conv (1x1 or 3x3 pad-1) as tiled implicit GEMM ----------------
// Output tile: 64 oc x 64 contiguous pixels within one image row (W=128 divisible by 64).
template<int IC, int OC, int TAPS>
__global__ __launch_bounds__(256)
void conv_kernel(const float* __restrict__ in, const float* __restrict__ w,
                 const float* __restrict__ bias, float* __restrict__ out) {
    __shared__ float As[16][64];
    __shared__ float Bs[16][64];

    const int tid  = threadIdx.x;
    const int tx   = tid & 15, ty = tid >> 4;
    const int p0   = blockIdx.x * 64;
    const int row  = p0 >> 7;
    const int col0 = p0 & 127;
    const int oc0  = blockIdx.y * 64;
    const int b    = blockIdx.z;

    float acc[4][4] = {};

    const int a_om = tid >> 2;          // 0..63
    const int a_kk = (tid & 3) << 2;    // 0,4,8,12
    const int b_kk = tid >> 4;          // 0..15
    const int b_pn = (tid & 15) << 2;   // 0..60

    for (int t = 0; t < TAPS; ++t) {
        const int dy = (TAPS == 9) ? (t / 3 - 1) : 0;
        const int dx = (TAPS == 9) ? (t % 3 - 1) : 0;
        const int row2 = row + dy;
        const bool rowok = (unsigned)row2 < (unsigned)HGT;

        for (int ic0 = 0; ic0 < IC; ic0 += 16) {
            // stage A: weights [16 ic x 64 oc]
            const float* wp = w + ((size_t)(oc0 + a_om) * IC + ic0 + a_kk) * TAPS + t;
            #pragma unroll
            for (int r2 = 0; r2 < 4; ++r2)
                As[a_kk + r2][a_om] = wp[r2 * TAPS];
            // stage B: input [16 ic x 64 px] with shift + zero pad
            const float* ip = in + (((size_t)b * IC + ic0 + b_kk) * HGT + row2) * WID;
            #pragma unroll
            for (int r2 = 0; r2 < 4; ++r2) {
                int c = col0 + b_pn + r2 + dx;
                Bs[b_kk][b_pn + r2] = (rowok && (unsigned)c < (unsigned)WID) ? ip[c] : 0.f;
            }
            __syncthreads();
            #pragma unroll
            for (int kk = 0; kk < 16; ++kk) {
                float4 av = *(const float4*)&As[kk][ty << 2];
                float4 bv = *(const float4*)&Bs[kk][tx << 2];
                float a[4] = {av.x, av.y, av.z, av.w};
                float bb[4] = {bv.x, bv.y, bv.z, bv.w};
                #pragma unroll
                for (int m = 0; m < 4; ++m)
                    #pragma unroll
                    for (int n = 0; n < 4; ++n)
                        acc[m][n] += a[m] * bb[n];
            }
            __syncthreads();
        }
    }

    #pragma unroll
    for (int m = 0; m < 4; ++m) {
        const int oc = oc0 + (ty << 2) + m;
        const float bv = bias[oc];
        float* op = out + ((size_t)b * OC + oc) * HW + p0 + (tx << 2);
        #pragma unroll
        for (int n = 0; n < 4; ++n)
            op[n] = acc[m][n] + bv;
    }
}

// ---------------- per-channel spatial L2 norm (q and k channels of y2) ----------------
__global__ __launch_bounds__(256)
void norm_kernel() {
    const int idx = blockIdx.x;          // b*256 + ch  (ch 0..127 = q, 128..255 = k)
    const int b = idx >> 8, ch = idx & 255;
    const float* p = g_y2 + ((size_t)b * OC2 + ch) * HW;
    float s = 0.f;
    for (int i = threadIdx.x; i < HW; i += 256) { float v = p[i]; s += v * v; }
    __shared__ float red[256];
    red[threadIdx.x] = s; __syncthreads();
    for (int o = 128; o; o >>= 1) {
        if (threadIdx.x < o) red[threadIdx.x] += red[threadIdx.x + o];
        __syncthreads();
    }
    if (threadIdx.x == 0) {
        float n = sqrtf(red[0]);
        g_invn[idx] = 1.f / fmaxf(n, 1e-12f);
    }
}

// ---------------- q.k^T partial dots (split over spatial for parallelism) ----------------
__global__ __launch_bounds__(256)
void qk_partial() {
    __shared__ float qs[32][65];
    __shared__ float ks[32][65];
    const int bh = blockIdx.y, sp = blockIdx.x;       // 8 x 32
    const int b = bh >> 2, h = bh & 3;
    const float* qbase = g_y2 + ((size_t)b * OC2 + h * CH) * HW + sp * 512;
    const float* kbase = g_y2 + ((size_t)b * OC2 + 128 + h * CH) * HW + sp * 512;
    const int tid = threadIdx.x;
    const int tc = tid >> 4, td = tid & 15;           // 2x2 micro-tile over 32x32
    float acc[2][2] = {};

    for (int s0 = 0; s0 < 512; s0 += 64) {
        for (int e = tid; e < 2048; e += 256) {
            int ch = e >> 6, ss = e & 63;
            qs[ch][ss] = qbase[(size_t)ch * HW + s0 + ss];
            ks[ch][ss] = kbase[(size_t)ch * HW + s0 + ss];
        }
        __syncthreads();
        #pragma unroll
        for (int ss = 0; ss < 64; ++ss) {
            float q0 = qs[2*tc][ss],   q1 = qs[2*tc+1][ss];
            float k0 = ks[2*td][ss],   k1 = ks[2*td+1][ss];
            acc[0][0] += q0*k0; acc[0][1] += q0*k1;
            acc[1][0] += q1*k0; acc[1][1] += q1*k1;
        }
        __syncthreads();
    }
    #pragma unroll
    for (int i2 = 0; i2 < 2; ++i2)
        #pragma unroll
        for (int j2 = 0; j2 < 2; ++j2)
            g_part[(((size_t)bh*32 + sp)*32 + 2*tc+i2)*32 + 2*td+j2] = acc[i2][j2];
}

// ---------------- reduce partials, scale by inv-norms & temperature, softmax over d ----------------
__global__ __launch_bounds__(1024)
void attn_softmax(const float* __restrict__ temp) {
    const int bh = blockIdx.x;
    const int b = bh >> 2, h = bh & 3;
    const int tid = threadIdx.x;
    const int c = tid >> 5, d = tid & 31;
    float s = 0.f;
    for (int sp = 0; sp < 32; ++sp)
        s += g_part[(((size_t)bh*32 + sp)*32 + c)*32 + d];
    s *= g_invn[b*256 + h*CH + c] * g_invn[b*256 + 128 + h*CH + d] * temp[h];
    // softmax over d = lane
    float m = s;
    #pragma unroll
    for (int o = 16; o; o >>= 1) m = fmaxf(m, __shfl_xor_sync(0xffffffffu, m, o));
    float e = __expf(s - m);
    float sum = e;
    #pragma unroll
    for (int o = 16; o; o >>= 1) sum += __shfl_xor_sync(0xffffffffu, sum, o);
    g_attn[((size_t)bh*32 + c)*32 + d] = e / sum;
}

// ---------------- out = attn @ v ----------------
__global__ __launch_bounds__(256)
void av_kernel() {
    __shared__ float sa[32][32];
    const int bh = blockIdx.y;
    const int b = bh >> 2, h = bh & 3;
    const int s = blockIdx.x * 256 + threadIdx.x;
    for (int e = threadIdx.x; e < 1024; e += 256)
        sa[e >> 5][e & 31] = g_attn[(size_t)bh*1024 + e];
    __syncthreads();
    const float* vbase = g_y2 + ((size_t)b * OC2 + 256 + h * CH) * HW + s;
    float acc[32];
    #pragma unroll
    for (int c = 0; c < 32; ++c) acc[c] = 0.f;
    #pragma unroll 8
    for (int d = 0; d < 32; ++d) {
        float vv = vbase[(size_t)d * HW];
        #pragma unroll
        for (int c = 0; c < 32; ++c) acc[c] += sa[c][d] * vv;
    }
    float* obase = g_o + ((size_t)b * DIM + h * CH) * HW + s;
    #pragma unroll
    for (int c = 0; c < 32; ++c) obase[(size_t)c * HW] = acc[c];
}

// ---------------- launch ----------------
extern "C" void kernel_launch(void* const* d_in, const int* in_sizes, int n_in,
                              void* d_out, int out_size) {
    const float* x      = (const float*)d_in[0];
    const float* qkv_r  = (const float*)d_in[1];
    const float* qkv_i  = (const float*)d_in[2];
    const float* qkv_j  = (const float*)d_in[3];
    const float* qkv_k  = (const float*)d_in[4];
    const float* qkv_b  = (const float*)d_in[5];
    const float* dw_r   = (const float*)d_in[6];
    const float* dw_i   = (const float*)d_in[7];
    const float* dw_j   = (const float*)d_in[8];
    const float* dw_k   = (const float*)d_in[9];
    const float* dw_b   = (const float*)d_in[10];
    const float* po_r   = (const float*)d_in[11];
    const float* po_i   = (const float*)d_in[12];
    const float* po_j   = (const float*)d_in[13];
    const float* po_k   = (const float*)d_in[14];
    const float* po_b   = (const float*)d_in[15];
    const float* temp   = (const float*)d_in[16];
    float* out = (float*)d_out;

    float *w1, *w2, *w3, *y1, *y2, *o;
    cudaGetSymbolAddress((void**)&w1, g_w1);
    cudaGetSymbolAddress((void**)&w2, g_w2);
    cudaGetSymbolAddress((void**)&w3, g_w3);
    cudaGetSymbolAddress((void**)&y1, g_y1);
    cudaGetSymbolAddress((void**)&y2, g_y2);
    cudaGetSymbolAddress((void**)&o,  g_o);

    // 1. expand quaternion weights
    expand_kernel<<<(OC1*IC1 + 255)/256, 256>>>(qkv_r, qkv_i, qkv_j, qkv_k, w1, 96, 32, 1, OC1*IC1);
    expand_kernel<<<(OC2*IC2*9 + 255)/256, 256>>>(dw_r, dw_i, dw_j, dw_k, w2, 96, 96, 9, OC2*IC2*9);
    expand_kernel<<<(OC3*IC3 + 255)/256, 256>>>(po_r, po_i, po_j, po_k, w3, 32, 32, 1, OC3*IC3);

    // 2. qkv 1x1 conv: x -> y1
    conv_kernel<IC1, OC1, 1><<<dim3(HW/64, OC1/64, BATCH), 256>>>(x, w1, qkv_b, y1);
    // 3. dw 3x3 conv: y1 -> y2  (dominant, ~173 GFLOP)
    conv_kernel<IC2, OC2, 9><<<dim3(HW/64, OC2/64, BATCH), 256>>>(y1, w2, dw_b, y2);

    // 4. norms for q, k
    norm_kernel<<<BATCH*256, 256>>>();
    // 5. q.k^T partials + reduce/scale/softmax
    qk_partial<<<dim3(32, 8), 256>>>();
    attn_softmax<<<8, 1024>>>(temp);
    // 6. attn @ v
    av_kernel<<<dim3(HW/256, 8), 256>>>();
    // 7. projection 1x1 conv: o -> d_out
    conv_kernel<IC3, OC3, 1><<<dim3(HW/64, OC3/64, BATCH), 256>>>(o, w3, po_b, out);
}

// round 8
// speedup vs baseline: 4.3115x; 4.3115x over previous
#include <cuda_runtime.h>
#include <cuda_bf16.h>
#include <cstdint>

// ---------------- problem constants ----------------
#define BATCH 2
#define DIM   128
#define HGT   128
#define WID   128
#define HW    (HGT*WID)        // 16384
#define HEADS 4
#define CH    32
#define OC1   384
#define IC1   128
#define OC2   384
#define IC2   384
#define OC3   128
#define IC3   128

// ---------------- device scratch ----------------
__device__ __align__(256) float g_w1[OC1*IC1];
__device__ __align__(256) float g_w3[OC3*IC3];
__device__ __align__(256) __nv_bfloat16 g_w2h[9*OC2*IC2];        // [t][oc][ic]
__device__ __align__(256) __nv_bfloat16 g_w2l[9*OC2*IC2];
__device__ __align__(256) __nv_bfloat16 g_y1h[BATCH*HW*IC2];     // [b][px][ic]
__device__ __align__(256) __nv_bfloat16 g_y1l[BATCH*HW*IC2];
__device__ __align__(256) float g_y2[BATCH*OC2*HW];              // [b][oc][px]
__device__ float g_invn[BATCH*256];
__device__ float g_part[8*32*32*32];
__device__ float g_attn[8*32*32];
__device__ __align__(256) float g_o[BATCH*DIM*HW];

// ---------------- helpers ----------------
__device__ __forceinline__ uint32_t smem_u32(const void* p) {
    uint32_t a;
    asm("{ .reg .u64 t; cvta.to.shared.u64 t, %1; cvt.u32.u64 %0, t; }" : "=r"(a) : "l"(p));
    return a;
}
#define SW128(x) ((x) ^ (((x) >> 3) & 0x70))

__device__ __forceinline__ void cpasync16(uint32_t dst, const void* src, int srcsize) {
    asm volatile("cp.async.ca.shared.global [%0], [%1], 16, %2;"
                 :: "r"(dst), "l"(src), "r"(srcsize));
}
__device__ __forceinline__ void ldsm4(uint32_t* r, uint32_t addr) {
    asm volatile("ldmatrix.sync.aligned.m8n8.x4.shared.b16 {%0,%1,%2,%3}, [%4];"
                 : "=r"(r[0]), "=r"(r[1]), "=r"(r[2]), "=r"(r[3]) : "r"(addr));
}
__device__ __forceinline__ void mma16816(float* c, const uint32_t* a, uint32_t b0, uint32_t b1) {
    asm volatile(
        "mma.sync.aligned.m16n8k16.row.col.f32.bf16.bf16.f32 "
        "{%0,%1,%2,%3}, {%4,%5,%6,%7}, {%8,%9}, {%0,%1,%2,%3};"
        : "+f"(c[0]), "+f"(c[1]), "+f"(c[2]), "+f"(c[3])
        : "r"(a[0]), "r"(a[1]), "r"(a[2]), "r"(a[3]), "r"(b0), "r"(b1));
}

// ---------------- quaternion weight expansion ----------------
__constant__ int   c_comp[16] = {0,1,2,3, 1,0,3,2, 2,3,0,1, 3,2,1,0};
__constant__ float c_sign[16] = {1,-1,-1,-1, 1,1,-1,1, 1,1,1,-1, 1,-1,1,1};

__global__ void expand1_kernel(const float* __restrict__ r, const float* __restrict__ i,
                               const float* __restrict__ j, const float* __restrict__ k,
                               float* __restrict__ W, int Co, int Ci, int total) {
    int idx = blockIdx.x * blockDim.x + threadIdx.x;
    if (idx >= total) return;
    int IC = 4 * Ci;
    int ic = idx % IC, oc = idx / IC;
    int br = oc / Co, o = oc % Co;
    int bc = ic / Ci, ci = ic % Ci;
    const float* comps[4] = {r, i, j, k};
    W[idx] = c_sign[br*4+bc] * comps[c_comp[br*4+bc]][o*Ci + ci];
}

__global__ void expand2_kernel(const float* __restrict__ r, const float* __restrict__ i,
                               const float* __restrict__ j, const float* __restrict__ k) {
    int idx = blockIdx.x * blockDim.x + threadIdx.x;
    if (idx >= 9*OC2*IC2) return;
    int t = idx / (OC2*IC2);
    int rest = idx % (OC2*IC2);
    int oc = rest / IC2, ic = rest % IC2;
    int br = oc / 96, o = oc % 96;
    int bc = ic / 96, ci = ic % 96;
    const float* comps[4] = {r, i, j, k};
    float v = c_sign[br*4+bc] * comps[c_comp[br*4+bc]][(o*96 + ci)*9 + t];
    __nv_bfloat16 hi = __float2bfloat16(v);
    __nv_bfloat16 lo = __float2bfloat16(v - __bfloat162float(hi));
    g_w2h[idx] = hi;
    g_w2l[idx] = lo;
}

// ---------------- qkv 1x1 conv (SIMT fp32) -> y1 bf16 hi/lo, [b][px][ic] ----------------
__global__ __launch_bounds__(256)
void conv1_kernel(const float* __restrict__ in, const float* __restrict__ w,
                  const float* __restrict__ bias) {
    __shared__ float As[16][64];
    __shared__ float Bs[16][64];
    const int tid = threadIdx.x;
    const int tx = tid & 15, ty = tid >> 4;
    const int p0 = blockIdx.x * 64;
    const int oc0 = blockIdx.y * 64;
    const int b = blockIdx.z;
    float acc[4][4] = {};
    const int a_om = tid >> 2, a_kk = (tid & 3) << 2;
    const int b_kk = tid >> 4, b_pn = (tid & 15) << 2;

    for (int ic0 = 0; ic0 < IC1; ic0 += 16) {
        const float* wp = w + (size_t)(oc0 + a_om) * IC1 + ic0 + a_kk;
        #pragma unroll
        for (int r2 = 0; r2 < 4; ++r2) As[a_kk + r2][a_om] = wp[r2];
        const float* ip = in + ((size_t)b * IC1 + ic0 + b_kk) * HW + p0;
        #pragma unroll
        for (int r2 = 0; r2 < 4; ++r2) Bs[b_kk][b_pn + r2] = ip[b_pn + r2];
        __syncthreads();
        #pragma unroll
        for (int kk = 0; kk < 16; ++kk) {
            float4 av = *(const float4*)&As[kk][ty << 2];
            float4 bv = *(const float4*)&Bs[kk][tx << 2];
            float a[4] = {av.x, av.y, av.z, av.w};
            float bb[4] = {bv.x, bv.y, bv.z, bv.w};
            #pragma unroll
            for (int m = 0; m < 4; ++m)
                #pragma unroll
                for (int n = 0; n < 4; ++n) acc[m][n] += a[m] * bb[n];
        }
        __syncthreads();
    }
    #pragma unroll
    for (int m = 0; m < 4; ++m) {
        const int oc = oc0 + (ty << 2) + m;
        const float bv = bias[oc];
        #pragma unroll
        for (int n = 0; n < 4; ++n) {
            float v = acc[m][n] + bv;
            size_t idx = ((size_t)b * HW + p0 + (tx << 2) + n) * IC2 + oc;
            __nv_bfloat16 hi = __float2bfloat16(v);
            g_y1h[idx] = hi;
            g_y1l[idx] = __float2bfloat16(v - __bfloat162float(hi));
        }
    }
}

// ---------------- dw 3x3 conv via warp-level mma.sync (split-bf16) ----------------
// C[128 oc x 128 px(one image row)] += sum over 9 taps x 384 ic of W^T stationary GEMM.
// SMEM buffer regions (per stage, 64KB): Ah 0, Al 16K, Bh 32K, Bl 48K; rows of 128B (64 ic bf16).
#define DW_BUF 65536

__global__ __launch_bounds__(256)
void dwconv_mma_kernel(const float* __restrict__ bias, float* __restrict__ y2) {
    extern __shared__ __align__(1024) char smem[];
    const uint32_t sbase = smem_u32(smem);
    const int tid = threadIdx.x;
    const int wid = tid >> 5, lane = tid & 31;
    const int b = blockIdx.z;
    const int oc0 = blockIdx.y * 128;
    const int r = blockIdx.x;                 // image row (0..127)

    const int wm = (wid >> 2) * 64;           // warp m offset (oc)
    const int wn = (wid & 3) * 32;            // warp n offset (px col)

    auto fill = [&](int s, int buf) {
        const int t = s / 6, ck = s % 6;
        const int dy = t / 3 - 1, dx = t % 3 - 1;
        const int ic0 = ck * 64;
        const uint32_t bufb = sbase + buf * DW_BUF;
        // A: weights, 2 halves x 128 rows x 8 chunks of 16B
        #pragma unroll
        for (int e = tid; e < 2048; e += 256) {
            const int half = e >> 10;
            const int row = (e >> 3) & 127, ch = e & 7;
            const __nv_bfloat16* src = (half ? g_w2l : g_w2h)
                + ((size_t)t * OC2 + oc0 + row) * IC2 + ic0 + ch * 8;
            cpasync16(bufb + half * 16384 + SW128((row << 7) + (ch << 4)), src, 16);
        }
        // B: y1 pixels of image row r+dy, col c+dx
        const int rr = r + dy;
        #pragma unroll
        for (int e = tid; e < 2048; e += 256) {
            const int half = e >> 10;
            const int row = (e >> 3) & 127, ch = e & 7;   // row = out col c
            const int cc = row + dx;
            const bool ok = ((unsigned)rr < 128u) && ((unsigned)cc < 128u);
            const __nv_bfloat16* src = (half ? g_y1l : g_y1h)
                + ((size_t)b * HW + (ok ? (rr << 7) + cc : 0)) * IC2 + ic0 + ch * 8;
            cpasync16(bufb + 32768 + half * 16384 + SW128((row << 7) + (ch << 4)), src, ok ? 16 : 0);
        }
        asm volatile("cp.async.commit_group;" ::: "memory");
    };

    float acc[4][4][4] = {};

    fill(0, 0);
    for (int s = 0; s < 54; ++s) {
        if (s < 53) {
            fill(s + 1, (s + 1) & 1);
            asm volatile("cp.async.wait_group 1;" ::: "memory");
        } else {
            asm volatile("cp.async.wait_group 0;" ::: "memory");
        }
        __syncthreads();
        const uint32_t bufb = sbase + (s & 1) * DW_BUF;
        const int rowA = lane & 15;
        const int koff = (lane >> 4) * 16;
        #pragma unroll
        for (int ks = 0; ks < 4; ++ks) {
            const int kb = ks * 32 + koff;
            uint32_t ah[4][4], al[4][4], bh[2][4], bl[2][4];
            #pragma unroll
            for (int mi = 0; mi < 4; ++mi) {
                const uint32_t off = SW128(((wm + mi * 16 + rowA) << 7) + kb);
                ldsm4(ah[mi], bufb + off);
                ldsm4(al[mi], bufb + 16384 + off);
            }
            #pragma unroll
            for (int nb = 0; nb < 2; ++nb) {
                const uint32_t off = SW128(((wn + nb * 16 + rowA) << 7) + kb);
                ldsm4(bh[nb], bufb + 32768 + off);
                ldsm4(bl[nb], bufb + 49152 + off);
            }
            #pragma unroll
            for (int mi = 0; mi < 4; ++mi) {
                #pragma unroll
                for (int nj = 0; nj < 4; ++nj) {
                    const int nb = nj >> 1, od = nj & 1;
                    mma16816(acc[mi][nj], ah[mi], bh[nb][od],     bh[nb][2 + od]);
                    mma16816(acc[mi][nj], ah[mi], bl[nb][od],     bl[nb][2 + od]);
                    mma16816(acc[mi][nj], al[mi], bh[nb][od],     bh[nb][2 + od]);
                }
            }
        }
        __syncthreads();
    }

    // epilogue: fragment (mi,nj): rows m=wm+mi*16+lane/4 (+8), cols n=wn+nj*8+(lane%4)*2
    const int mrow = lane >> 2;
    const int ncol = (lane & 3) * 2;
    #pragma unroll
    for (int mi = 0; mi < 4; ++mi) {
        const int m0 = oc0 + wm + mi * 16 + mrow;
        const float bv0 = bias[m0];
        const float bv1 = bias[m0 + 8];
        float* base0 = y2 + (((size_t)b * OC2 + m0) << 14) + (r << 7);
        float* base1 = base0 + ((size_t)8 << 14);
        #pragma unroll
        for (int nj = 0; nj < 4; ++nj) {
            const int n = wn + nj * 8 + ncol;
            float2 v0 = make_float2(acc[mi][nj][0] + bv0, acc[mi][nj][1] + bv0);
            float2 v1 = make_float2(acc[mi][nj][2] + bv1, acc[mi][nj][3] + bv1);
            *(float2*)(base0 + n) = v0;
            *(float2*)(base1 + n) = v1;
        }
    }
}

// ---------------- generic 1x1 SIMT conv (final projection) ----------------
template<int IC, int OC>
__global__ __launch_bounds__(256)
void conv1x1_kernel(const float* __restrict__ in, const float* __restrict__ w,
                    const float* __restrict__ bias, float* __restrict__ out) {
    __shared__ float As[16][64];
    __shared__ float Bs[16][64];
    const int tid = threadIdx.x;
    const int tx = tid & 15, ty = tid >> 4;
    const int p0 = blockIdx.x * 64;
    const int oc0 = blockIdx.y * 64;
    const int b = blockIdx.z;
    float acc[4][4] = {};
    const int a_om = tid >> 2, a_kk = (tid & 3) << 2;
    const int b_kk = tid >> 4, b_pn = (tid & 15) << 2;
    for (int ic0 = 0; ic0 < IC; ic0 += 16) {
        const float* wp = w + (size_t)(oc0 + a_om) * IC + ic0 + a_kk;
        #pragma unroll
        for (int r2 = 0; r2 < 4; ++r2) As[a_kk + r2][a_om] = wp[r2];
        const float* ip = in + ((size_t)b * IC + ic0 + b_kk) * HW + p0;
        #pragma unroll
        for (int r2 = 0; r2 < 4; ++r2) Bs[b_kk][b_pn + r2] = ip[b_pn + r2];
        __syncthreads();
        #pragma unroll
        for (int kk = 0; kk < 16; ++kk) {
            float4 av = *(const float4*)&As[kk][ty << 2];
            float4 bv = *(const float4*)&Bs[kk][tx << 2];
            float a[4] = {av.x, av.y, av.z, av.w};
            float bb[4] = {bv.x, bv.y, bv.z, bv.w};
            #pragma unroll
            for (int m = 0; m < 4; ++m)
                #pragma unroll
                for (int n = 0; n < 4; ++n) acc[m][n] += a[m] * bb[n];
        }
        __syncthreads();
    }
    #pragma unroll
    for (int m = 0; m < 4; ++m) {
        const int oc = oc0 + (ty << 2) + m;
        const float bv = bias[oc];
        float* op = out + ((size_t)b * OC + oc) * HW + p0 + (tx << 2);
        #pragma unroll
        for (int n = 0; n < 4; ++n) op[n] = acc[m][n] + bv;
    }
}

// ---------------- attention stages ----------------
__global__ __launch_bounds__(256)
void norm_kernel() {
    const int idx = blockIdx.x;
    const int b = idx >> 8, ch = idx & 255;
    const float* p = g_y2 + ((size_t)b * OC2 + ch) * HW;
    float s = 0.f;
    for (int i = threadIdx.x; i < HW; i += 256) { float v = p[i]; s += v * v; }
    __shared__ float red[256];
    red[threadIdx.x] = s; __syncthreads();
    for (int o = 128; o; o >>= 1) {
        if (threadIdx.x < o) red[threadIdx.x] += red[threadIdx.x + o];
        __syncthreads();
    }
    if (threadIdx.x == 0) g_invn[idx] = 1.f / fmaxf(sqrtf(red[0]), 1e-12f);
}

__global__ __launch_bounds__(256)
void qk_partial() {
    __shared__ float qs[32][65];
    __shared__ float ks[32][65];
    const int bh = blockIdx.y, sp = blockIdx.x;
    const int b = bh >> 2, h = bh & 3;
    const float* qbase = g_y2 + ((size_t)b * OC2 + h * CH) * HW + sp * 512;
    const float* kbase = g_y2 + ((size_t)b * OC2 + 128 + h * CH) * HW + sp * 512;
    const int tid = threadIdx.x;
    const int tc = tid >> 4, td = tid & 15;
    float acc[2][2] = {};
    for (int s0 = 0; s0 < 512; s0 += 64) {
        for (int e = tid; e < 2048; e += 256) {
            int ch = e >> 6, ss = e & 63;
            qs[ch][ss] = qbase[(size_t)ch * HW + s0 + ss];
            ks[ch][ss] = kbase[(size_t)ch * HW + s0 + ss];
        }
        __syncthreads();
        #pragma unroll
        for (int ss = 0; ss < 64; ++ss) {
            float q0 = qs[2*tc][ss], q1 = qs[2*tc+1][ss];
            float k0 = ks[2*td][ss], k1 = ks[2*td+1][ss];
            acc[0][0] += q0*k0; acc[0][1] += q0*k1;
            acc[1][0] += q1*k0; acc[1][1] += q1*k1;
        }
        __syncthreads();
    }
    #pragma unroll
    for (int i2 = 0; i2 < 2; ++i2)
        #pragma unroll
        for (int j2 = 0; j2 < 2; ++j2)
            g_part[(((size_t)bh*32 + sp)*32 + 2*tc+i2)*32 + 2*td+j2] = acc[i2][j2];
}

__global__ __launch_bounds__(1024)
void attn_softmax(const float* __restrict__ temp) {
    const int bh = blockIdx.x;
    const int b = bh >> 2, h = bh & 3;
    const int tid = threadIdx.x;
    const int c = tid >> 5, d = tid & 31;
    float s = 0.f;
    for (int sp = 0; sp < 32; ++sp)
        s += g_part[(((size_t)bh*32 + sp)*32 + c)*32 + d];
    s *= g_invn[b*256 + h*CH + c] * g_invn[b*256 + 128 + h*CH + d] * temp[h];
    float m = s;
    #pragma unroll
    for (int o = 16; o; o >>= 1) m = fmaxf(m, __shfl_xor_sync(0xffffffffu, m, o));
    float e = __expf(s - m);
    float sum = e;
    #pragma unroll
    for (int o = 16; o; o >>= 1) sum += __shfl_xor_sync(0xffffffffu, sum, o);
    g_attn[((size_t)bh*32 + c)*32 + d] = e / sum;
}

__global__ __launch_bounds__(256)
void av_kernel() {
    __shared__ float sa[32][32];
    const int bh = blockIdx.y;
    const int b = bh >> 2, h = bh & 3;
    const int s = blockIdx.x * 256 + threadIdx.x;
    for (int e = threadIdx.x; e < 1024; e += 256)
        sa[e >> 5][e & 31] = g_attn[(size_t)bh*1024 + e];
    __syncthreads();
    const float* vbase = g_y2 + ((size_t)b * OC2 + 256 + h * CH) * HW + s;
    float acc[32];
    #pragma unroll
    for (int c = 0; c < 32; ++c) acc[c] = 0.f;
    #pragma unroll 8
    for (int d = 0; d < 32; ++d) {
        float vv = vbase[(size_t)d * HW];
        #pragma unroll
        for (int c = 0; c < 32; ++c) acc[c] += sa[c][d] * vv;
    }
    float* obase = g_o + ((size_t)b * DIM + h * CH) * HW + s;
    #pragma unroll
    for (int c = 0; c < 32; ++c) obase[(size_t)c * HW] = acc[c];
}

// ---------------- launch ----------------
extern "C" void kernel_launch(void* const* d_in, const int* in_sizes, int n_in,
                              void* d_out, int out_size) {
    const float* x     = (const float*)d_in[0];
    const float* qkv_r = (const float*)d_in[1];
    const float* qkv_i = (const float*)d_in[2];
    const float* qkv_j = (const float*)d_in[3];
    const float* qkv_k = (const float*)d_in[4];
    const float* qkv_b = (const float*)d_in[5];
    const float* dw_r  = (const float*)d_in[6];
    const float* dw_i  = (const float*)d_in[7];
    const float* dw_j  = (const float*)d_in[8];
    const float* dw_k  = (const float*)d_in[9];
    const float* dw_b  = (const float*)d_in[10];
    const float* po_r  = (const float*)d_in[11];
    const float* po_i  = (const float*)d_in[12];
    const float* po_j  = (const float*)d_in[13];
    const float* po_k  = (const float*)d_in[14];
    const float* po_b  = (const float*)d_in[15];
    const float* temp  = (const float*)d_in[16];
    float* out = (float*)d_out;

    float *w1, *w3, *y2, *o;
    cudaGetSymbolAddress((void**)&w1, g_w1);
    cudaGetSymbolAddress((void**)&w3, g_w3);
    cudaGetSymbolAddress((void**)&y2, g_y2);
    cudaGetSymbolAddress((void**)&o,  g_o);

    cudaFuncSetAttribute(dwconv_mma_kernel, cudaFuncAttributeMaxDynamicSharedMemorySize, 2 * DW_BUF);

    // 1. weight expansion
    expand1_kernel<<<(OC1*IC1 + 255)/256, 256>>>(qkv_r, qkv_i, qkv_j, qkv_k, w1, 96, 32, OC1*IC1);
    expand2_kernel<<<(9*OC2*IC2 + 255)/256, 256>>>(dw_r, dw_i, dw_j, dw_k);
    expand1_kernel<<<(OC3*IC3 + 255)/256, 256>>>(po_r, po_i, po_j, po_k, w3, 32, 32, OC3*IC3);

    // 2. qkv 1x1 conv -> y1 (bf16 hi/lo, [px][ic])
    conv1_kernel<<<dim3(HW/64, OC1/64, BATCH), 256>>>(x, w1, qkv_b);

    // 3. dw 3x3 conv via mma.sync -> y2 fp32
    dwconv_mma_kernel<<<dim3(HGT, OC2/128, BATCH), 256, 2 * DW_BUF>>>(dw_b, y2);

    // 4-6. attention
    norm_kernel<<<BATCH*256, 256>>>();
    qk_partial<<<dim3(32, 8), 256>>>();
    attn_softmax<<<8, 1024>>>(temp);
    av_kernel<<<dim3(HW/256, 8), 256>>>();

    // 7. projection 1x1 conv
    conv1x1_kernel<IC3, OC3><<<dim3(HW/64, OC3/64, BATCH), 256>>>(o, w3, po_b, out);
}

// round 12
// speedup vs baseline: 4.7556x; 1.1030x over previous
#include <cuda_runtime.h>
#include <cuda_bf16.h>
#include <cstdint>

// ---------------- problem constants ----------------
#define BATCH 2
#define DIM   128
#define HGT   128
#define WID   128
#define HW    (HGT*WID)        // 16384
#define HEADS 4
#define CH    32
#define OC1   384
#define IC1   128
#define OC2   384
#define IC2   384
#define OC3   128
#define IC3   128

// ---------------- device scratch ----------------
__device__ __align__(256) __nv_bfloat16 g_w1h[OC1*IC1];          // [oc][ic]
__device__ __align__(256) __nv_bfloat16 g_w1l[OC1*IC1];
__device__ __align__(256) __nv_bfloat16 g_w3h[OC3*IC3];
__device__ __align__(256) __nv_bfloat16 g_w3l[OC3*IC3];
__device__ __align__(256) __nv_bfloat16 g_w2h[9*OC2*IC2];        // [t][oc][ic]
__device__ __align__(256) __nv_bfloat16 g_w2l[9*OC2*IC2];
__device__ __align__(256) __nv_bfloat16 g_xh[BATCH*HW*IC1];      // [b][px][ic]
__device__ __align__(256) __nv_bfloat16 g_xl[BATCH*HW*IC1];
__device__ __align__(256) __nv_bfloat16 g_y1h[BATCH*HW*IC2];     // [b][px][ic]
__device__ __align__(256) __nv_bfloat16 g_y1l[BATCH*HW*IC2];
__device__ __align__(256) float g_y2[BATCH*OC2*HW];              // [b][oc][px]
__device__ __align__(256) __nv_bfloat16 g_oh[BATCH*HW*DIM];      // [b][px][c]
__device__ __align__(256) __nv_bfloat16 g_ol[BATCH*HW*DIM];
__device__ float g_nsq[8*32*64];                                 // [bh][sp][q32|k32]
__device__ float g_part[8*32*32*32];
__device__ float g_attn[8*32*32];

// ---------------- helpers ----------------
__device__ __forceinline__ uint32_t smem_u32(const void* p) {
    uint32_t a;
    asm("{ .reg .u64 t; cvta.to.shared.u64 t, %1; cvt.u32.u64 %0, t; }" : "=r"(a) : "l"(p));
    return a;
}
#define SW128(x) ((x) ^ (((x) >> 3) & 0x70))

__device__ __forceinline__ void cpasync16(uint32_t dst, const void* src, int srcsize) {
    asm volatile("cp.async.ca.shared.global [%0], [%1], 16, %2;"
                 :: "r"(dst), "l"(src), "r"(srcsize));
}
__device__ __forceinline__ void ldsm4(uint32_t* r, uint32_t addr) {
    asm volatile("ldmatrix.sync.aligned.m8n8.x4.shared.b16 {%0,%1,%2,%3}, [%4];"
                 : "=r"(r[0]), "=r"(r[1]), "=r"(r[2]), "=r"(r[3]) : "r"(addr));
}
__device__ __forceinline__ void mma16816(float* c, const uint32_t* a, uint32_t b0, uint32_t b1) {
    asm volatile(
        "mma.sync.aligned.m16n8k16.row.col.f32.bf16.bf16.f32 "
        "{%0,%1,%2,%3}, {%4,%5,%6,%7}, {%8,%9}, {%0,%1,%2,%3};"
        : "+f"(c[0]), "+f"(c[1]), "+f"(c[2]), "+f"(c[3])
        : "r"(a[0]), "r"(a[1]), "r"(a[2]), "r"(a[3]), "r"(b0), "r"(b1));
}
__device__ __forceinline__ __nv_bfloat162 split_pair_hi(float a, float b) {
    return __nv_bfloat162(__float2bfloat16(a), __float2bfloat16(b));
}
__device__ __forceinline__ __nv_bfloat162 split_pair_lo(float a, float b) {
    __nv_bfloat16 ha = __float2bfloat16(a), hb = __float2bfloat16(b);
    return __nv_bfloat162(__float2bfloat16(a - __bfloat162float(ha)),
                          __float2bfloat16(b - __bfloat162float(hb)));
}

// ---------------- quaternion weight expansion ----------------
__constant__ int   c_comp[16] = {0,1,2,3, 1,0,3,2, 2,3,0,1, 3,2,1,0};
__constant__ float c_sign[16] = {1,-1,-1,-1, 1,1,-1,1, 1,1,1,-1, 1,-1,1,1};

// bf16 hi/lo [oc][ic] (1x1 taps)
__global__ void expand_bf16_kernel(const float* __restrict__ r, const float* __restrict__ i,
                                   const float* __restrict__ j, const float* __restrict__ k,
                                   __nv_bfloat16* __restrict__ Wh, __nv_bfloat16* __restrict__ Wl,
                                   int Co, int Ci, int total) {
    int idx = blockIdx.x * blockDim.x + threadIdx.x;
    if (idx >= total) return;
    int IC = 4 * Ci;
    int ic = idx % IC, oc = idx / IC;
    int br = oc / Co, o = oc % Co;
    int bc = ic / Ci, ci = ic % Ci;
    const float* comps[4] = {r, i, j, k};
    float v = c_sign[br*4+bc] * comps[c_comp[br*4+bc]][o*Ci + ci];
    __nv_bfloat16 hi = __float2bfloat16(v);
    Wh[idx] = hi;
    Wl[idx] = __float2bfloat16(v - __bfloat162float(hi));
}

__global__ void expand2_kernel(const float* __restrict__ r, const float* __restrict__ i,
                               const float* __restrict__ j, const float* __restrict__ k) {
    int idx = blockIdx.x * blockDim.x + threadIdx.x;
    if (idx >= 9*OC2*IC2) return;
    int t = idx / (OC2*IC2);
    int rest = idx % (OC2*IC2);
    int oc = rest / IC2, ic = rest % IC2;
    int br = oc / 96, o = oc % 96;
    int bc = ic / 96, ci = ic % 96;
    const float* comps[4] = {r, i, j, k};
    float v = c_sign[br*4+bc] * comps[c_comp[br*4+bc]][(o*96 + ci)*9 + t];
    __nv_bfloat16 hi = __float2bfloat16(v);
    g_w2h[idx] = hi;
    g_w2l[idx] = __float2bfloat16(v - __bfloat162float(hi));
}

// ---------------- x transpose + bf16 split: [b][ic][px] fp32 -> [b][px][ic] hi/lo ----------------
__global__ __launch_bounds__(256)
void convert_x_kernel(const float* __restrict__ x) {
    __shared__ float t[32][33];
    const int b = blockIdx.z;
    const int px0 = blockIdx.x * 32, ic0 = blockIdx.y * 32;
    const int tx = threadIdx.x, ty = threadIdx.y;   // (32, 8)
    #pragma unroll
    for (int i0 = 0; i0 < 32; i0 += 8)
        t[i0 + ty][tx] = x[((size_t)b * IC1 + ic0 + i0 + ty) * HW + px0 + tx];
    __syncthreads();
    #pragma unroll
    for (int i0 = 0; i0 < 32; i0 += 8) {
        float v = t[tx][i0 + ty];
        __nv_bfloat16 hi = __float2bfloat16(v);
        size_t idx = ((size_t)b * HW + px0 + i0 + ty) * IC1 + ic0 + tx;
        g_xh[idx] = hi;
        g_xl[idx] = __float2bfloat16(v - __bfloat162float(hi));
    }
}

// ---------------- qkv 1x1 conv via mma.sync: C[px 128][oc 128] ----------------
// SMEM 128KB: Ah 0 (x), Al 32K, Bh 64K (w1), Bl 96K; each region 2 ck-chunks of 128 rows x 128B.
__global__ __launch_bounds__(256)
void qkv_mma_kernel(const float* __restrict__ bias) {
    extern __shared__ __align__(1024) char smem[];
    const uint32_t sbase = smem_u32(smem);
    const int tid = threadIdx.x;
    const int wid = tid >> 5, lane = tid & 31;
    const int b = blockIdx.z;
    const int oc0 = blockIdx.y * 128;
    const int px0 = blockIdx.x * 128;
    const int wm = (wid >> 2) * 64;   // px
    const int wn = (wid & 3) * 32;    // oc

    for (int e = tid; e < 8192; e += 256) {
        const int region = e >> 11;
        const int rem = e & 2047;
        const int ck = rem >> 10, row = (rem >> 3) & 127, ch = rem & 7;
        const uint32_t dst = sbase + region * 32768 + ck * 16384 + SW128((row << 7) + (ch << 4));
        const __nv_bfloat16* src;
        if (region < 2)
            src = (region ? g_xl : g_xh) + ((size_t)b * HW + px0 + row) * IC1 + ck * 64 + ch * 8;
        else
            src = (region == 3 ? g_w1l : g_w1h) + (size_t)(oc0 + row) * IC1 + ck * 64 + ch * 8;
        cpasync16(dst, src, 16);
    }
    asm volatile("cp.async.commit_group;" ::: "memory");
    asm volatile("cp.async.wait_group 0;" ::: "memory");
    __syncthreads();

    float acc[4][4][4] = {};
    const int rowA = lane & 15;
    const int koff = (lane >> 4) * 16;
    #pragma unroll
    for (int ck = 0; ck < 2; ++ck) {
        const uint32_t a_h = sbase + ck * 16384;
        const uint32_t a_l = a_h + 32768;
        const uint32_t b_h = a_h + 65536;
        const uint32_t b_l = a_h + 98304;
        #pragma unroll
        for (int ks = 0; ks < 4; ++ks) {
            const int kb = ks * 32 + koff;
            uint32_t ah[4][4], al[4][4], bh[2][4], bl[2][4];
            #pragma unroll
            for (int mi = 0; mi < 4; ++mi) {
                const uint32_t off = SW128(((wm + mi * 16 + rowA) << 7) + kb);
                ldsm4(ah[mi], a_h + off);
                ldsm4(al[mi], a_l + off);
            }
            #pragma unroll
            for (int nb = 0; nb < 2; ++nb) {
                const uint32_t off = SW128(((wn + nb * 16 + rowA) << 7) + kb);
                ldsm4(bh[nb], b_h + off);
                ldsm4(bl[nb], b_l + off);
            }
            #pragma unroll
            for (int mi = 0; mi < 4; ++mi)
                #pragma unroll
                for (int nj = 0; nj < 4; ++nj) {
                    const int nb = nj >> 1, od = nj & 1;
                    mma16816(acc[mi][nj], ah[mi], bh[nb][od], bh[nb][2 + od]);
                    mma16816(acc[mi][nj], ah[mi], bl[nb][od], bl[nb][2 + od]);
                    mma16816(acc[mi][nj], al[mi], bh[nb][od], bh[nb][2 + od]);
                }
        }
    }

    // epilogue: m = px, n = oc (pairs contiguous) -> y1 hi/lo [px][oc]
    const int mrow = lane >> 2;
    const int ncol = (lane & 3) * 2;
    #pragma unroll
    for (int mi = 0; mi < 4; ++mi) {
        const int m0 = px0 + wm + mi * 16 + mrow;
        #pragma unroll
        for (int nj = 0; nj < 4; ++nj) {
            const int n = oc0 + wn + nj * 8 + ncol;
            const float b0 = bias[n], b1 = bias[n + 1];
            float v0 = acc[mi][nj][0] + b0, v1 = acc[mi][nj][1] + b1;
            float v2 = acc[mi][nj][2] + b0, v3 = acc[mi][nj][3] + b1;
            size_t i0 = ((size_t)b * HW + m0) * IC2 + n;
            size_t i1 = ((size_t)b * HW + m0 + 8) * IC2 + n;
            *(__nv_bfloat162*)(g_y1h + i0) = split_pair_hi(v0, v1);
            *(__nv_bfloat162*)(g_y1l + i0) = split_pair_lo(v0, v1);
            *(__nv_bfloat162*)(g_y1h + i1) = split_pair_hi(v2, v3);
            *(__nv_bfloat162*)(g_y1l + i1) = split_pair_lo(v2, v3);
        }
    }
}

// ---------------- dw 3x3 conv via warp-level mma.sync (split-bf16) ----------------
#define DW_BUF 65536

__global__ __launch_bounds__(256)
void dwconv_mma_kernel(const float* __restrict__ bias, float* __restrict__ y2) {
    extern __shared__ __align__(1024) char smem[];
    const uint32_t sbase = smem_u32(smem);
    const int tid = threadIdx.x;
    const int wid = tid >> 5, lane = tid & 31;
    const int b = blockIdx.z;
    const int oc0 = blockIdx.y * 128;
    const int r = blockIdx.x;

    const int wm = (wid >> 2) * 64;
    const int wn = (wid & 3) * 32;

    auto fill = [&](int s, int buf) {
        const int t = s / 6, ck = s % 6;
        const int dy = t / 3 - 1, dx = t % 3 - 1;
        const int ic0 = ck * 64;
        const uint32_t bufb = sbase + buf * DW_BUF;
        #pragma unroll
        for (int e = tid; e < 2048; e += 256) {
            const int half = e >> 10;
            const int row = (e >> 3) & 127, ch = e & 7;
            const __nv_bfloat16* src = (half ? g_w2l : g_w2h)
                + ((size_t)t * OC2 + oc0 + row) * IC2 + ic0 + ch * 8;
            cpasync16(bufb + half * 16384 + SW128((row << 7) + (ch << 4)), src, 16);
        }
        const int rr = r + dy;
        #pragma unroll
        for (int e = tid; e < 2048; e += 256) {
            const int half = e >> 10;
            const int row = (e >> 3) & 127, ch = e & 7;
            const int cc = row + dx;
            const bool ok = ((unsigned)rr < 128u) && ((unsigned)cc < 128u);
            const __nv_bfloat16* src = (half ? g_y1l : g_y1h)
                + ((size_t)b * HW + (ok ? (rr << 7) + cc : 0)) * IC2 + ic0 + ch * 8;
            cpasync16(bufb + 32768 + half * 16384 + SW128((row << 7) + (ch << 4)), src, ok ? 16 : 0);
        }
        asm volatile("cp.async.commit_group;" ::: "memory");
    };

    float acc[4][4][4] = {};

    fill(0, 0);
    for (int s = 0; s < 54; ++s) {
        if (s < 53) {
            fill(s + 1, (s + 1) & 1);
            asm volatile("cp.async.wait_group 1;" ::: "memory");
        } else {
            asm volatile("cp.async.wait_group 0;" ::: "memory");
        }
        __syncthreads();
        const uint32_t bufb = sbase + (s & 1) * DW_BUF;
        const int rowA = lane & 15;
        const int koff = (lane >> 4) * 16;
        #pragma unroll
        for (int ks = 0; ks < 4; ++ks) {
            const int kb = ks * 32 + koff;
            uint32_t ah[4][4], al[4][4], bh[2][4], bl[2][4];
            #pragma unroll
            for (int mi = 0; mi < 4; ++mi) {
                const uint32_t off = SW128(((wm + mi * 16 + rowA) << 7) + kb);
                ldsm4(ah[mi], bufb + off);
                ldsm4(al[mi], bufb + 16384 + off);
            }
            #pragma unroll
            for (int nb = 0; nb < 2; ++nb) {
                const uint32_t off = SW128(((wn + nb * 16 + rowA) << 7) + kb);
                ldsm4(bh[nb], bufb + 32768 + off);
                ldsm4(bl[nb], bufb + 49152 + off);
            }
            #pragma unroll
            for (int mi = 0; mi < 4; ++mi) {
                #pragma unroll
                for (int nj = 0; nj < 4; ++nj) {
                    const int nb = nj >> 1, od = nj & 1;
                    mma16816(acc[mi][nj], ah[mi], bh[nb][od], bh[nb][2 + od]);
                    mma16816(acc[mi][nj], ah[mi], bl[nb][od], bl[nb][2 + od]);
                    mma16816(acc[mi][nj], al[mi], bh[nb][od], bh[nb][2 + od]);
                }
            }
        }
        __syncthreads();
    }

    const int mrow = lane >> 2;
    const int ncol = (lane & 3) * 2;
    #pragma unroll
    for (int mi = 0; mi < 4; ++mi) {
        const int m0 = oc0 + wm + mi * 16 + mrow;
        const float bv0 = bias[m0];
        const float bv1 = bias[m0 + 8];
        float* base0 = y2 + (((size_t)b * OC2 + m0) << 14) + (r << 7);
        float* base1 = base0 + ((size_t)8 << 14);
        #pragma unroll
        for (int nj = 0; nj < 4; ++nj) {
            const int n = wn + nj * 8 + ncol;
            float2 v0 = make_float2(acc[mi][nj][0] + bv0, acc[mi][nj][1] + bv0);
            float2 v1 = make_float2(acc[mi][nj][2] + bv1, acc[mi][nj][3] + bv1);
            *(float2*)(base0 + n) = v0;
            *(float2*)(base1 + n) = v1;
        }
    }
}

// ---------------- projection 1x1 via mma.sync: C[oc 128][px 128] -> d_out ----------------
__global__ __launch_bounds__(256)
void proj_mma_kernel(const float* __restrict__ bias, float* __restrict__ out) {
    extern __shared__ __align__(1024) char smem[];
    const uint32_t sbase = smem_u32(smem);
    const int tid = threadIdx.x;
    const int wid = tid >> 5, lane = tid & 31;
    const int b = blockIdx.z;
    const int px0 = blockIdx.x * 128;
    const int wm = (wid >> 2) * 64;   // oc
    const int wn = (wid & 3) * 32;    // px

    for (int e = tid; e < 8192; e += 256) {
        const int region = e >> 11;
        const int rem = e & 2047;
        const int ck = rem >> 10, row = (rem >> 3) & 127, ch = rem & 7;
        const uint32_t dst = sbase + region * 32768 + ck * 16384 + SW128((row << 7) + (ch << 4));
        const __nv_bfloat16* src;
        if (region < 2)
            src = (region ? g_w3l : g_w3h) + (size_t)row * IC3 + ck * 64 + ch * 8;
        else
            src = (region == 3 ? g_ol : g_oh) + ((size_t)b * HW + px0 + row) * DIM + ck * 64 + ch * 8;
        cpasync16(dst, src, 16);
    }
    asm volatile("cp.async.commit_group;" ::: "memory");
    asm volatile("cp.async.wait_group 0;" ::: "memory");
    __syncthreads();

    float acc[4][4][4] = {};
    const int rowA = lane & 15;
    const int koff = (lane >> 4) * 16;
    #pragma unroll
    for (int ck = 0; ck < 2; ++ck) {
        const uint32_t a_h = sbase + ck * 16384;
        const uint32_t a_l = a_h + 32768;
        const uint32_t b_h = a_h + 65536;
        const uint32_t b_l = a_h + 98304;
        #pragma unroll
        for (int ks = 0; ks < 4; ++ks) {
            const int kb = ks * 32 + koff;
            uint32_t ah[4][4], al[4][4], bh[2][4], bl[2][4];
            #pragma unroll
            for (int mi = 0; mi < 4; ++mi) {
                const uint32_t off = SW128(((wm + mi * 16 + rowA) << 7) + kb);
                ldsm4(ah[mi], a_h + off);
                ldsm4(al[mi], a_l + off);
            }
            #pragma unroll
            for (int nb = 0; nb < 2; ++nb) {
                const uint32_t off = SW128(((wn + nb * 16 + rowA) << 7) + kb);
                ldsm4(bh[nb], b_h + off);
                ldsm4(bl[nb], b_l + off);
            }
            #pragma unroll
            for (int mi = 0; mi < 4; ++mi)
                #pragma unroll
                for (int nj = 0; nj < 4; ++nj) {
                    const int nb = nj >> 1, od = nj & 1;
                    mma16816(acc[mi][nj], ah[mi], bh[nb][od], bh[nb][2 + od]);
                    mma16816(acc[mi][nj], ah[mi], bl[nb][od], bl[nb][2 + od]);
                    mma16816(acc[mi][nj], al[mi], bh[nb][od], bh[nb][2 + od]);
                }
        }
    }

    // epilogue: m = oc, n = px -> out[b][oc][px]
    const int mrow = lane >> 2;
    const int ncol = (lane & 3) * 2;
    #pragma unroll
    for (int mi = 0; mi < 4; ++mi) {
        const int m0 = wm + mi * 16 + mrow;
        const float bv0 = bias[m0];
        const float bv1 = bias[m0 + 8];
        float* base0 = out + (((size_t)b * OC3 + m0) << 14) + px0;
        float* base1 = base0 + ((size_t)8 << 14);
        #pragma unroll
        for (int nj = 0; nj < 4; ++nj) {
            const int n = wn + nj * 8 + ncol;
            float2 v0 = make_float2(acc[mi][nj][0] + bv0, acc[mi][nj][1] + bv0);
            float2 v1 = make_float2(acc[mi][nj][2] + bv1, acc[mi][nj][3] + bv1);
            *(float2*)(base0 + n) = v0;
            *(float2*)(base1 + n) = v1;
        }
    }
}

// ---------------- qk partial dots + fused norm partials ----------------
__global__ __launch_bounds__(256)
void qk_partial() {
    __shared__ float qs[32][65];
    __shared__ float ks[32][65];
    __shared__ float rbuf[256];
    const int bh = blockIdx.y, sp = blockIdx.x;
    const int b = bh >> 2, h = bh & 3;
    const float* qbase = g_y2 + ((size_t)b * OC2 + h * CH) * HW + sp * 512;
    const float* kbase = g_y2 + ((size_t)b * OC2 + 128 + h * CH) * HW + sp * 512;
    const int tid = threadIdx.x;
    const int tc = tid >> 4, td = tid & 15;
    const int role = tid >> 7;            // 0 = q, 1 = k
    const int chn = (tid >> 2) & 31;
    const int seg = tid & 3;
    float acc[2][2] = {};
    float sq = 0.f;
    for (int s0 = 0; s0 < 512; s0 += 64) {
        for (int e = tid; e < 2048; e += 256) {
            int ch = e >> 6, ss = e & 63;
            qs[ch][ss] = qbase[(size_t)ch * HW + s0 + ss];
            ks[ch][ss] = kbase[(size_t)ch * HW + s0 + ss];
        }
        __syncthreads();
        {
            const float* tp = role ? &ks[chn][0] : &qs[chn][0];
            #pragma unroll
            for (int ii = 0; ii < 16; ++ii) {
                float v = tp[seg * 16 + ii];
                sq += v * v;
            }
        }
        #pragma unroll
        for (int ss = 0; ss < 64; ++ss) {
            float q0 = qs[2*tc][ss], q1 = qs[2*tc+1][ss];
            float k0 = ks[2*td][ss], k1 = ks[2*td+1][ss];
            acc[0][0] += q0*k0; acc[0][1] += q0*k1;
            acc[1][0] += q1*k0; acc[1][1] += q1*k1;
        }
        __syncthreads();
    }
    rbuf[tid] = sq;
    __syncthreads();
    if (seg == 0)
        g_nsq[((size_t)bh*32 + sp)*64 + (tid >> 2)] =
            rbuf[tid] + rbuf[tid+1] + rbuf[tid+2] + rbuf[tid+3];
    #pragma unroll
    for (int i2 = 0; i2 < 2; ++i2)
        #pragma unroll
        for (int j2 = 0; j2 < 2; ++j2)
            g_part[(((size_t)bh*32 + sp)*32 + 2*tc+i2)*32 + 2*td+j2] = acc[i2][j2];
}

__global__ __launch_bounds__(1024)
void attn_softmax(const float* __restrict__ temp) {
    __shared__ float invn[64];
    const int bh = blockIdx.x;
    const int h = bh & 3;
    const int tid = threadIdx.x;
    const int c = tid >> 5, d = tid & 31;
    float s = 0.f;
    for (int sp = 0; sp < 32; ++sp)
        s += g_part[(((size_t)bh*32 + sp)*32 + c)*32 + d];
    if (tid < 64) {
        float t = 0.f;
        for (int sp = 0; sp < 32; ++sp)
            t += g_nsq[((size_t)bh*32 + sp)*64 + tid];
        invn[tid] = 1.f / fmaxf(sqrtf(t), 1e-12f);
    }
    __syncthreads();
    s *= invn[c] * invn[32 + d] * temp[h];
    float m = s;
    #pragma unroll
    for (int o = 16; o; o >>= 1) m = fmaxf(m, __shfl_xor_sync(0xffffffffu, m, o));
    float e = __expf(s - m);
    float sum = e;
    #pragma unroll
    for (int o = 16; o; o >>= 1) sum += __shfl_xor_sync(0xffffffffu, sum, o);
    g_attn[((size_t)bh*32 + c)*32 + d] = e / sum;
}

// ---------------- out = attn @ v -> o hi/lo [b][px][c] ----------------
__global__ __launch_bounds__(256)
void av_kernel() {
    __shared__ float sa[32][32];
    const int bh = blockIdx.y;
    const int b = bh >> 2, h = bh & 3;
    const int s = blockIdx.x * 256 + threadIdx.x;
    for (int e = threadIdx.x; e < 1024; e += 256)
        sa[e >> 5][e & 31] = g_attn[(size_t)bh*1024 + e];
    __syncthreads();
    const float* vbase = g_y2 + ((size_t)b * OC2 + 256 + h * CH) * HW + s;
    float acc[32];
    #pragma unroll
    for (int c = 0; c < 32; ++c) acc[c] = 0.f;
    #pragma unroll 8
    for (int d = 0; d < 32; ++d) {
        float vv = vbase[(size_t)d * HW];
        #pragma unroll
        for (int c = 0; c < 32; ++c) acc[c] += sa[c][d] * vv;
    }
    __nv_bfloat16* oh = g_oh + ((size_t)b * HW + s) * DIM + h * 32;
    __nv_bfloat16* ol = g_ol + ((size_t)b * HW + s) * DIM + h * 32;
    #pragma unroll
    for (int c = 0; c < 32; c += 2) {
        *(__nv_bfloat162*)(oh + c) = split_pair_hi(acc[c], acc[c+1]);
        *(__nv_bfloat162*)(ol + c) = split_pair_lo(acc[c], acc[c+1]);
    }
}

// ---------------- launch ----------------
extern "C" void kernel_launch(void* const* d_in, const int* in_sizes, int n_in,
                              void* d_out, int out_size) {
    const float* x     = (const float*)d_in[0];
    const float* qkv_r = (const float*)d_in[1];
    const float* qkv_i = (const float*)d_in[2];
    const float* qkv_j = (const float*)d_in[3];
    const float* qkv_k = (const float*)d_in[4];
    const float* qkv_b = (const float*)d_in[5];
    const float* dw_r  = (const float*)d_in[6];
    const float* dw_i  = (const float*)d_in[7];
    const float* dw_j  = (const float*)d_in[8];
    const float* dw_k  = (const float*)d_in[9];
    const float* dw_b  = (const float*)d_in[10];
    const float* po_r  = (const float*)d_in[11];
    const float* po_i  = (const float*)d_in[12];
    const float* po_j  = (const float*)d_in[13];
    const float* po_k  = (const float*)d_in[14];
    const float* po_b  = (const float*)d_in[15];
    const float* temp  = (const float*)d_in[16];
    float* out = (float*)d_out;

    __nv_bfloat16 *w1h, *w1l, *w3h, *w3l;
    float *y2;
    cudaGetSymbolAddress((void**)&w1h, g_w1h);
    cudaGetSymbolAddress((void**)&w1l, g_w1l);
    cudaGetSymbolAddress((void**)&w3h, g_w3h);
    cudaGetSymbolAddress((void**)&w3l, g_w3l);
    cudaGetSymbolAddress((void**)&y2,  g_y2);

    cudaFuncSetAttribute(dwconv_mma_kernel, cudaFuncAttributeMaxDynamicSharedMemorySize, 2 * DW_BUF);
    cudaFuncSetAttribute(qkv_mma_kernel,    cudaFuncAttributeMaxDynamicSharedMemorySize, 131072);
    cudaFuncSetAttribute(proj_mma_kernel,   cudaFuncAttributeMaxDynamicSharedMemorySize, 131072);

    // 1. weight expansion + x convert
    expand_bf16_kernel<<<(OC1*IC1 + 255)/256, 256>>>(qkv_r, qkv_i, qkv_j, qkv_k, w1h, w1l, 96, 32, OC1*IC1);
    expand2_kernel<<<(9*OC2*IC2 + 255)/256, 256>>>(dw_r, dw_i, dw_j, dw_k);
    expand_bf16_kernel<<<(OC3*IC3 + 255)/256, 256>>>(po_r, po_i, po_j, po_k, w3h, w3l, 32, 32, OC3*IC3);
    convert_x_kernel<<<dim3(HW/32, IC1/32, BATCH), dim3(32, 8)>>>(x);

    // 2. qkv 1x1 conv (mma) -> y1 hi/lo [px][ic]
    qkv_mma_kernel<<<dim3(HW/128, OC1/128, BATCH), 256, 131072>>>(qkv_b);

    // 3. dw 3x3 conv (mma) -> y2 fp32
    dwconv_mma_kernel<<<dim3(HGT, OC2/128, BATCH), 256, 2 * DW_BUF>>>(dw_b, y2);

    // 4-6. attention (norms fused into qk)
    qk_partial<<<dim3(32, 8), 256>>>();
    attn_softmax<<<8, 1024>>>(temp);
    av_kernel<<<dim3(HW/256, 8), 256>>>();

    // 7. projection (mma) -> d_out
    proj_mma_kernel<<<dim3(HW/128, 1, BATCH), 256, 131072>>>(po_b, out);
}

// round 13
// speedup vs baseline: 5.0863x; 1.0695x over previous
#include <cuda_runtime.h>
#include <cuda_bf16.h>
#include <cstdint>

// ---------------- problem constants ----------------
#define BATCH 2
#define DIM   128
#define HGT   128
#define WID   128
#define HW    (HGT*WID)        // 16384
#define HEADS 4
#define CH    32
#define OC1   384
#define IC1   128
#define OC2   384
#define IC2   384
#define OC3   128
#define IC3   128

// ---------------- device scratch ----------------
__device__ __align__(256) __nv_bfloat16 g_w1h[OC1*IC1];          // [oc][ic]
__device__ __align__(256) __nv_bfloat16 g_w1l[OC1*IC1];
__device__ __align__(256) __nv_bfloat16 g_w3h[OC3*IC3];
__device__ __align__(256) __nv_bfloat16 g_w3l[OC3*IC3];
__device__ __align__(256) __nv_bfloat16 g_w2h[9*OC2*IC2];        // [t][oc][ic]
__device__ __align__(256) __nv_bfloat16 g_w2l[9*OC2*IC2];
__device__ __align__(256) __nv_bfloat16 g_xh[BATCH*HW*IC1];      // [b][px][ic]
__device__ __align__(256) __nv_bfloat16 g_xl[BATCH*HW*IC1];
__device__ __align__(256) __nv_bfloat16 g_y1h[BATCH*HW*IC2];     // [b][px][ic]
__device__ __align__(256) __nv_bfloat16 g_y1l[BATCH*HW*IC2];
__device__ __align__(256) float g_y2[BATCH*OC2*HW];              // [b][oc][px]
__device__ __align__(256) __nv_bfloat16 g_oh[BATCH*HW*DIM];      // [b][px][c]
__device__ __align__(256) __nv_bfloat16 g_ol[BATCH*HW*DIM];
__device__ float g_nsq[8*32*64];                                 // [bh][sp][q32|k32]
__device__ float g_part[8*32*32*32];
__device__ float g_attn[8*32*32];

// ---------------- helpers ----------------
__device__ __forceinline__ uint32_t smem_u32(const void* p) {
    uint32_t a;
    asm("{ .reg .u64 t; cvta.to.shared.u64 t, %1; cvt.u32.u64 %0, t; }" : "=r"(a) : "l"(p));
    return a;
}
#define SW128(x) ((x) ^ (((x) >> 3) & 0x70))

__device__ __forceinline__ void cpasync16(uint32_t dst, const void* src, int srcsize) {
    asm volatile("cp.async.ca.shared.global [%0], [%1], 16, %2;"
                 :: "r"(dst), "l"(src), "r"(srcsize));
}
__device__ __forceinline__ void ldsm4(uint32_t* r, uint32_t addr) {
    asm volatile("ldmatrix.sync.aligned.m8n8.x4.shared.b16 {%0,%1,%2,%3}, [%4];"
                 : "=r"(r[0]), "=r"(r[1]), "=r"(r[2]), "=r"(r[3]) : "r"(addr));
}
__device__ __forceinline__ void mma16816(float* c, const uint32_t* a, uint32_t b0, uint32_t b1) {
    asm volatile(
        "mma.sync.aligned.m16n8k16.row.col.f32.bf16.bf16.f32 "
        "{%0,%1,%2,%3}, {%4,%5,%6,%7}, {%8,%9}, {%0,%1,%2,%3};"
        : "+f"(c[0]), "+f"(c[1]), "+f"(c[2]), "+f"(c[3])
        : "r"(a[0]), "r"(a[1]), "r"(a[2]), "r"(a[3]), "r"(b0), "r"(b1));
}
__device__ __forceinline__ __nv_bfloat162 split_pair_hi(float a, float b) {
    return __nv_bfloat162(__float2bfloat16(a), __float2bfloat16(b));
}
__device__ __forceinline__ __nv_bfloat162 split_pair_lo(float a, float b) {
    __nv_bfloat16 ha = __float2bfloat16(a), hb = __float2bfloat16(b);
    return __nv_bfloat162(__float2bfloat16(a - __bfloat162float(ha)),
                          __float2bfloat16(b - __bfloat162float(hb)));
}

// ---------------- quaternion weight expansion ----------------
__constant__ int   c_comp[16] = {0,1,2,3, 1,0,3,2, 2,3,0,1, 3,2,1,0};
__constant__ float c_sign[16] = {1,-1,-1,-1, 1,1,-1,1, 1,1,1,-1, 1,-1,1,1};

__global__ void expand_bf16_kernel(const float* __restrict__ r, const float* __restrict__ i,
                                   const float* __restrict__ j, const float* __restrict__ k,
                                   __nv_bfloat16* __restrict__ Wh, __nv_bfloat16* __restrict__ Wl,
                                   int Co, int Ci, int total) {
    int idx = blockIdx.x * blockDim.x + threadIdx.x;
    if (idx >= total) return;
    int IC = 4 * Ci;
    int ic = idx % IC, oc = idx / IC;
    int br = oc / Co, o = oc % Co;
    int bc = ic / Ci, ci = ic % Ci;
    const float* comps[4] = {r, i, j, k};
    float v = c_sign[br*4+bc] * comps[c_comp[br*4+bc]][o*Ci + ci];
    __nv_bfloat16 hi = __float2bfloat16(v);
    Wh[idx] = hi;
    Wl[idx] = __float2bfloat16(v - __bfloat162float(hi));
}

__global__ void expand2_kernel(const float* __restrict__ r, const float* __restrict__ i,
                               const float* __restrict__ j, const float* __restrict__ k) {
    int idx = blockIdx.x * blockDim.x + threadIdx.x;
    if (idx >= 9*OC2*IC2) return;
    int t = idx / (OC2*IC2);
    int rest = idx % (OC2*IC2);
    int oc = rest / IC2, ic = rest % IC2;
    int br = oc / 96, o = oc % 96;
    int bc = ic / 96, ci = ic % 96;
    const float* comps[4] = {r, i, j, k};
    float v = c_sign[br*4+bc] * comps[c_comp[br*4+bc]][(o*96 + ci)*9 + t];
    __nv_bfloat16 hi = __float2bfloat16(v);
    g_w2h[idx] = hi;
    g_w2l[idx] = __float2bfloat16(v - __bfloat162float(hi));
}

// ---------------- x transpose + bf16 split ----------------
__global__ __launch_bounds__(256)
void convert_x_kernel(const float* __restrict__ x) {
    __shared__ float t[32][33];
    const int b = blockIdx.z;
    const int px0 = blockIdx.x * 32, ic0 = blockIdx.y * 32;
    const int tx = threadIdx.x, ty = threadIdx.y;   // (32, 8)
    #pragma unroll
    for (int i0 = 0; i0 < 32; i0 += 8)
        t[i0 + ty][tx] = x[((size_t)b * IC1 + ic0 + i0 + ty) * HW + px0 + tx];
    __syncthreads();
    #pragma unroll
    for (int i0 = 0; i0 < 32; i0 += 8) {
        float v = t[tx][i0 + ty];
        __nv_bfloat16 hi = __float2bfloat16(v);
        size_t idx = ((size_t)b * HW + px0 + i0 + ty) * IC1 + ic0 + tx;
        g_xh[idx] = hi;
        g_xl[idx] = __float2bfloat16(v - __bfloat162float(hi));
    }
}

// ---------------- qkv 1x1 conv via mma.sync ----------------
__global__ __launch_bounds__(256)
void qkv_mma_kernel(const float* __restrict__ bias) {
    extern __shared__ __align__(1024) char smem[];
    const uint32_t sbase = smem_u32(smem);
    const int tid = threadIdx.x;
    const int wid = tid >> 5, lane = tid & 31;
    const int b = blockIdx.z;
    const int oc0 = blockIdx.y * 128;
    const int px0 = blockIdx.x * 128;
    const int wm = (wid >> 2) * 64;   // px
    const int wn = (wid & 3) * 32;    // oc

    for (int e = tid; e < 8192; e += 256) {
        const int region = e >> 11;
        const int rem = e & 2047;
        const int ck = rem >> 10, row = (rem >> 3) & 127, ch = rem & 7;
        const uint32_t dst = sbase + region * 32768 + ck * 16384 + SW128((row << 7) + (ch << 4));
        const __nv_bfloat16* src;
        if (region < 2)
            src = (region ? g_xl : g_xh) + ((size_t)b * HW + px0 + row) * IC1 + ck * 64 + ch * 8;
        else
            src = (region == 3 ? g_w1l : g_w1h) + (size_t)(oc0 + row) * IC1 + ck * 64 + ch * 8;
        cpasync16(dst, src, 16);
    }
    asm volatile("cp.async.commit_group;" ::: "memory");
    asm volatile("cp.async.wait_group 0;" ::: "memory");
    __syncthreads();

    float acc[4][4][4] = {};
    const int rowA = lane & 15;
    const int koff = (lane >> 4) * 16;
    #pragma unroll
    for (int ck = 0; ck < 2; ++ck) {
        const uint32_t a_h = sbase + ck * 16384;
        const uint32_t a_l = a_h + 32768;
        const uint32_t b_h = a_h + 65536;
        const uint32_t b_l = a_h + 98304;
        #pragma unroll
        for (int ks = 0; ks < 4; ++ks) {
            const int kb = ks * 32 + koff;
            uint32_t ah[4][4], al[4][4], bh[2][4], bl[2][4];
            #pragma unroll
            for (int mi = 0; mi < 4; ++mi) {
                const uint32_t off = SW128(((wm + mi * 16 + rowA) << 7) + kb);
                ldsm4(ah[mi], a_h + off);
                ldsm4(al[mi], a_l + off);
            }
            #pragma unroll
            for (int nb = 0; nb < 2; ++nb) {
                const uint32_t off = SW128(((wn + nb * 16 + rowA) << 7) + kb);
                ldsm4(bh[nb], b_h + off);
                ldsm4(bl[nb], b_l + off);
            }
            #pragma unroll
            for (int mi = 0; mi < 4; ++mi)
                #pragma unroll
                for (int nj = 0; nj < 4; ++nj) {
                    const int nb = nj >> 1, od = nj & 1;
                    mma16816(acc[mi][nj], ah[mi], bh[nb][od], bh[nb][2 + od]);
                    mma16816(acc[mi][nj], ah[mi], bl[nb][od], bl[nb][2 + od]);
                    mma16816(acc[mi][nj], al[mi], bh[nb][od], bh[nb][2 + od]);
                }
        }
    }

    const int mrow = lane >> 2;
    const int ncol = (lane & 3) * 2;
    #pragma unroll
    for (int mi = 0; mi < 4; ++mi) {
        const int m0 = px0 + wm + mi * 16 + mrow;
        #pragma unroll
        for (int nj = 0; nj < 4; ++nj) {
            const int n = oc0 + wn + nj * 8 + ncol;
            const float b0 = bias[n], b1 = bias[n + 1];
            float v0 = acc[mi][nj][0] + b0, v1 = acc[mi][nj][1] + b1;
            float v2 = acc[mi][nj][2] + b0, v3 = acc[mi][nj][3] + b1;
            size_t i0 = ((size_t)b * HW + m0) * IC2 + n;
            size_t i1 = ((size_t)b * HW + m0 + 8) * IC2 + n;
            *(__nv_bfloat162*)(g_y1h + i0) = split_pair_hi(v0, v1);
            *(__nv_bfloat162*)(g_y1l + i0) = split_pair_lo(v0, v1);
            *(__nv_bfloat162*)(g_y1h + i1) = split_pair_hi(v2, v3);
            *(__nv_bfloat162*)(g_y1l + i1) = split_pair_lo(v2, v3);
        }
    }
}

// ---------------- dw 3x3 conv: window-reuse, N=256, split-bf16 ----------------
// Per CTA: output 128 oc x 256 px (2 image rows). Loop: ic-chunk (6) outer, taps (9) inner.
// B = 4-row x 130-col y1 window per chunk (hi+lo), reused by all 9 taps via shifted ldsm rows.
// A = weight tile per (tap, chunk), double-buffered.
#define A_STG   32768                   // per A stage: hi 16K + lo 16K
#define B_HALF  66560                   // 520 rows * 128 B
#define SM_B    65536                   // B window offset (after 2 A stages)
#define DW_SMEM (SM_B + 2*B_HALF)       // 198656

__global__ __launch_bounds__(256)
void dwconv_mma_kernel(const float* __restrict__ bias, float* __restrict__ y2) {
    extern __shared__ __align__(1024) char smem[];
    const uint32_t sbase = smem_u32(smem);
    const int tid = threadIdx.x;
    const int wid = tid >> 5, lane = tid & 31;
    const int b = blockIdx.z;
    const int oc0 = blockIdx.y * 128;
    const int r0 = blockIdx.x * 2;            // first of 2 output rows

    const int wm = (wid & 1) * 64;            // oc block (2)
    const int wn = (wid >> 1) * 64;           // px block (4) over 256
    const int row_local = wn >> 7;            // 0 or 1
    const int col0 = wn & 127;

    auto fill_A = [&](int t, int ck, int buf) {
        #pragma unroll
        for (int e = tid; e < 2048; e += 256) {
            const int half = e >> 10;
            const int row = (e >> 3) & 127, ch = e & 7;
            const __nv_bfloat16* src = (half ? g_w2l : g_w2h)
                + ((size_t)t * OC2 + oc0 + row) * IC2 + ck * 64 + ch * 8;
            cpasync16(sbase + buf * A_STG + half * 16384 + SW128((row << 7) + (ch << 4)), src, 16);
        }
        asm volatile("cp.async.commit_group;" ::: "memory");
    };

    auto fill_B = [&](int ck) {
        // 2 halves x 520 rows (4 wrow x 130 col) x 8 chunks of 16B
        for (int e = tid; e < 8320; e += 256) {
            const int half = e / 4160;
            const int rem = e - half * 4160;
            const int w = rem >> 3, ch = rem & 7;
            const int wrow = w / 130;
            const int colidx = w - wrow * 130;
            const int rr = r0 - 1 + wrow;
            const int cc = colidx - 1;
            const bool ok = ((unsigned)rr < 128u) && ((unsigned)cc < 128u);
            const __nv_bfloat16* src = (half ? g_y1l : g_y1h)
                + ((size_t)b * HW + (ok ? (rr << 7) + cc : 0)) * IC2 + ck * 64 + ch * 8;
            cpasync16(sbase + SM_B + half * B_HALF + SW128((w << 7) + (ch << 4)), src, ok ? 16 : 0);
        }
        asm volatile("cp.async.commit_group;" ::: "memory");
    };

    float acc[4][8][4] = {};
    const int rowA = lane & 15;
    const int koff = (lane >> 4) * 16;

    for (int ck = 0; ck < 6; ++ck) {
        fill_B(ck);
        fill_A(0, ck, 0);
        for (int t = 0; t < 9; ++t) {
            if (t < 8) {
                fill_A(t + 1, ck, (t + 1) & 1);
                asm volatile("cp.async.wait_group 1;" ::: "memory");
            } else {
                asm volatile("cp.async.wait_group 0;" ::: "memory");
            }
            __syncthreads();
            const int dy = t / 3 - 1, dx = t % 3 - 1;
            const uint32_t bufA = sbase + (t & 1) * A_STG;
            // B base row for this warp+tap (row index within 520-row window)
            const int wbase = (row_local + dy + 1) * 130 + col0 + dx + 1;
            #pragma unroll
            for (int ks = 0; ks < 4; ++ks) {
                const int kb = ks * 32 + koff;
                uint32_t ah[4][4], al[4][4], bh[4][4], bl[4][4];
                #pragma unroll
                for (int mi = 0; mi < 4; ++mi) {
                    const uint32_t off = SW128(((wm + mi * 16 + rowA) << 7) + kb);
                    ldsm4(ah[mi], bufA + off);
                    ldsm4(al[mi], bufA + 16384 + off);
                }
                #pragma unroll
                for (int nb = 0; nb < 4; ++nb) {
                    const uint32_t off = SW128(((wbase + nb * 16 + rowA) << 7) + kb);
                    ldsm4(bh[nb], sbase + SM_B + off);
                    ldsm4(bl[nb], sbase + SM_B + B_HALF + off);
                }
                #pragma unroll
                for (int mi = 0; mi < 4; ++mi)
                    #pragma unroll
                    for (int nj = 0; nj < 8; ++nj) {
                        const int nb = nj >> 1, od = nj & 1;
                        mma16816(acc[mi][nj], ah[mi], bh[nb][od], bh[nb][2 + od]);
                        mma16816(acc[mi][nj], ah[mi], bl[nb][od], bl[nb][2 + od]);
                        mma16816(acc[mi][nj], al[mi], bh[nb][od], bh[nb][2 + od]);
                    }
            }
            __syncthreads();
        }
    }

    // epilogue: m = oc local, n = px local (0..255 across 2 rows, contiguous in y2)
    const int mrow = lane >> 2;
    const int ncol = (lane & 3) * 2;
    #pragma unroll
    for (int mi = 0; mi < 4; ++mi) {
        const int m0 = oc0 + wm + mi * 16 + mrow;
        const float bv0 = bias[m0];
        const float bv1 = bias[m0 + 8];
        float* base0 = y2 + (((size_t)b * OC2 + m0) << 14) + (r0 << 7);
        float* base1 = base0 + ((size_t)8 << 14);
        #pragma unroll
        for (int nj = 0; nj < 8; ++nj) {
            const int n = wn + nj * 8 + ncol;
            float2 v0 = make_float2(acc[mi][nj][0] + bv0, acc[mi][nj][1] + bv0);
            float2 v1 = make_float2(acc[mi][nj][2] + bv1, acc[mi][nj][3] + bv1);
            *(float2*)(base0 + n) = v0;
            *(float2*)(base1 + n) = v1;
        }
    }
}

// ---------------- projection 1x1 via mma.sync ----------------
__global__ __launch_bounds__(256)
void proj_mma_kernel(const float* __restrict__ bias, float* __restrict__ out) {
    extern __shared__ __align__(1024) char smem[];
    const uint32_t sbase = smem_u32(smem);
    const int tid = threadIdx.x;
    const int wid = tid >> 5, lane = tid & 31;
    const int b = blockIdx.z;
    const int px0 = blockIdx.x * 128;
    const int wm = (wid >> 2) * 64;   // oc
    const int wn = (wid & 3) * 32;    // px

    for (int e = tid; e < 8192; e += 256) {
        const int region = e >> 11;
        const int rem = e & 2047;
        const int ck = rem >> 10, row = (rem >> 3) & 127, ch = rem & 7;
        const uint32_t dst = sbase + region * 32768 + ck * 16384 + SW128((row << 7) + (ch << 4));
        const __nv_bfloat16* src;
        if (region < 2)
            src = (region ? g_w3l : g_w3h) + (size_t)row * IC3 + ck * 64 + ch * 8;
        else
            src = (region == 3 ? g_ol : g_oh) + ((size_t)b * HW + px0 + row) * DIM + ck * 64 + ch * 8;
        cpasync16(dst, src, 16);
    }
    asm volatile("cp.async.commit_group;" ::: "memory");
    asm volatile("cp.async.wait_group 0;" ::: "memory");
    __syncthreads();

    float acc[4][4][4] = {};
    const int rowA = lane & 15;
    const int koff = (lane >> 4) * 16;
    #pragma unroll
    for (int ck = 0; ck < 2; ++ck) {
        const uint32_t a_h = sbase + ck * 16384;
        const uint32_t a_l = a_h + 32768;
        const uint32_t b_h = a_h + 65536;
        const uint32_t b_l = a_h + 98304;
        #pragma unroll
        for (int ks = 0; ks < 4; ++ks) {
            const int kb = ks * 32 + koff;
            uint32_t ah[4][4], al[4][4], bh[2][4], bl[2][4];
            #pragma unroll
            for (int mi = 0; mi < 4; ++mi) {
                const uint32_t off = SW128(((wm + mi * 16 + rowA) << 7) + kb);
                ldsm4(ah[mi], a_h + off);
                ldsm4(al[mi], a_l + off);
            }
            #pragma unroll
            for (int nb = 0; nb < 2; ++nb) {
                const uint32_t off = SW128(((wn + nb * 16 + rowA) << 7) + kb);
                ldsm4(bh[nb], b_h + off);
                ldsm4(bl[nb], b_l + off);
            }
            #pragma unroll
            for (int mi = 0; mi < 4; ++mi)
                #pragma unroll
                for (int nj = 0; nj < 4; ++nj) {
                    const int nb = nj >> 1, od = nj & 1;
                    mma16816(acc[mi][nj], ah[mi], bh[nb][od], bh[nb][2 + od]);
                    mma16816(acc[mi][nj], ah[mi], bl[nb][od], bl[nb][2 + od]);
                    mma16816(acc[mi][nj], al[mi], bh[nb][od], bh[nb][2 + od]);
                }
        }
    }

    const int mrow = lane >> 2;
    const int ncol = (lane & 3) * 2;
    #pragma unroll
    for (int mi = 0; mi < 4; ++mi) {
        const int m0 = wm + mi * 16 + mrow;
        const float bv0 = bias[m0];
        const float bv1 = bias[m0 + 8];
        float* base0 = out + (((size_t)b * OC3 + m0) << 14) + px0;
        float* base1 = base0 + ((size_t)8 << 14);
        #pragma unroll
        for (int nj = 0; nj < 4; ++nj) {
            const int n = wn + nj * 8 + ncol;
            float2 v0 = make_float2(acc[mi][nj][0] + bv0, acc[mi][nj][1] + bv0);
            float2 v1 = make_float2(acc[mi][nj][2] + bv1, acc[mi][nj][3] + bv1);
            *(float2*)(base0 + n) = v0;
            *(float2*)(base1 + n) = v1;
        }
    }
}

// ---------------- qk partial dots + fused norm partials ----------------
__global__ __launch_bounds__(256)
void qk_partial() {
    __shared__ float qs[32][65];
    __shared__ float ks[32][65];
    __shared__ float rbuf[256];
    const int bh = blockIdx.y, sp = blockIdx.x;
    const int b = bh >> 2, h = bh & 3;
    const float* qbase = g_y2 + ((size_t)b * OC2 + h * CH) * HW + sp * 512;
    const float* kbase = g_y2 + ((size_t)b * OC2 + 128 + h * CH) * HW + sp * 512;
    const int tid = threadIdx.x;
    const int tc = tid >> 4, td = tid & 15;
    const int role = tid >> 7;
    const int chn = (tid >> 2) & 31;
    const int seg = tid & 3;
    float acc[2][2] = {};
    float sq = 0.f;
    for (int s0 = 0; s0 < 512; s0 += 64) {
        for (int e = tid; e < 2048; e += 256) {
            int ch = e >> 6, ss = e & 63;
            qs[ch][ss] = qbase[(size_t)ch * HW + s0 + ss];
            ks[ch][ss] = kbase[(size_t)ch * HW + s0 + ss];
        }
        __syncthreads();
        {
            const float* tp = role ? &ks[chn][0] : &qs[chn][0];
            #pragma unroll
            for (int ii = 0; ii < 16; ++ii) {
                float v = tp[seg * 16 + ii];
                sq += v * v;
            }
        }
        #pragma unroll
        for (int ss = 0; ss < 64; ++ss) {
            float q0 = qs[2*tc][ss], q1 = qs[2*tc+1][ss];
            float k0 = ks[2*td][ss], k1 = ks[2*td+1][ss];
            acc[0][0] += q0*k0; acc[0][1] += q0*k1;
            acc[1][0] += q1*k0; acc[1][1] += q1*k1;
        }
        __syncthreads();
    }
    rbuf[tid] = sq;
    __syncthreads();
    if (seg == 0)
        g_nsq[((size_t)bh*32 + sp)*64 + (tid >> 2)] =
            rbuf[tid] + rbuf[tid+1] + rbuf[tid+2] + rbuf[tid+3];
    #pragma unroll
    for (int i2 = 0; i2 < 2; ++i2)
        #pragma unroll
        for (int j2 = 0; j2 < 2; ++j2)
            g_part[(((size_t)bh*32 + sp)*32 + 2*tc+i2)*32 + 2*td+j2] = acc[i2][j2];
}

__global__ __launch_bounds__(1024)
void attn_softmax(const float* __restrict__ temp) {
    __shared__ float invn[64];
    const int bh = blockIdx.x;
    const int h = bh & 3;
    const int tid = threadIdx.x;
    const int c = tid >> 5, d = tid & 31;
    float s = 0.f;
    for (int sp = 0; sp < 32; ++sp)
        s += g_part[(((size_t)bh*32 + sp)*32 + c)*32 + d];
    if (tid < 64) {
        float t = 0.f;
        for (int sp = 0; sp < 32; ++sp)
            t += g_nsq[((size_t)bh*32 + sp)*64 + tid];
        invn[tid] = 1.f / fmaxf(sqrtf(t), 1e-12f);
    }
    __syncthreads();
    s *= invn[c] * invn[32 + d] * temp[h];
    float m = s;
    #pragma unroll
    for (int o = 16; o; o >>= 1) m = fmaxf(m, __shfl_xor_sync(0xffffffffu, m, o));
    float e = __expf(s - m);
    float sum = e;
    #pragma unroll
    for (int o = 16; o; o >>= 1) sum += __shfl_xor_sync(0xffffffffu, sum, o);
    g_attn[((size_t)bh*32 + c)*32 + d] = e / sum;
}

// ---------------- out = attn @ v -> o hi/lo [b][px][c] ----------------
__global__ __launch_bounds__(256)
void av_kernel() {
    __shared__ float sa[32][32];
    const int bh = blockIdx.y;
    const int b = bh >> 2, h = bh & 3;
    const int s = blockIdx.x * 256 + threadIdx.x;
    for (int e = threadIdx.x; e < 1024; e += 256)
        sa[e >> 5][e & 31] = g_attn[(size_t)bh*1024 + e];
    __syncthreads();
    const float* vbase = g_y2 + ((size_t)b * OC2 + 256 + h * CH) * HW + s;
    float acc[32];
    #pragma unroll
    for (int c = 0; c < 32; ++c) acc[c] = 0.f;
    #pragma unroll 8
    for (int d = 0; d < 32; ++d) {
        float vv = vbase[(size_t)d * HW];
        #pragma unroll
        for (int c = 0; c < 32; ++c) acc[c] += sa[c][d] * vv;
    }
    __nv_bfloat16* oh = g_oh + ((size_t)b * HW + s) * DIM + h * 32;
    __nv_bfloat16* ol = g_ol + ((size_t)b * HW + s) * DIM + h * 32;
    #pragma unroll
    for (int c = 0; c < 32; c += 2) {
        *(__nv_bfloat162*)(oh + c) = split_pair_hi(acc[c], acc[c+1]);
        *(__nv_bfloat162*)(ol + c) = split_pair_lo(acc[c], acc[c+1]);
    }
}

// ---------------- launch ----------------
extern "C" void kernel_launch(void* const* d_in, const int* in_sizes, int n_in,
                              void* d_out, int out_size) {
    const float* x     = (const float*)d_in[0];
    const float* qkv_r = (const float*)d_in[1];
    const float* qkv_i = (const float*)d_in[2];
    const float* qkv_j = (const float*)d_in[3];
    const float* qkv_k = (const float*)d_in[4];
    const float* qkv_b = (const float*)d_in[5];
    const float* dw_r  = (const float*)d_in[6];
    const float* dw_i  = (const float*)d_in[7];
    const float* dw_j  = (const float*)d_in[8];
    const float* dw_k  = (const float*)d_in[9];
    const float* dw_b  = (const float*)d_in[10];
    const float* po_r  = (const float*)d_in[11];
    const float* po_i  = (const float*)d_in[12];
    const float* po_j  = (const float*)d_in[13];
    const float* po_k  = (const float*)d_in[14];
    const float* po_b  = (const float*)d_in[15];
    const float* temp  = (const float*)d_in[16];
    float* out = (float*)d_out;

    __nv_bfloat16 *w1h, *w1l, *w3h, *w3l;
    float *y2;
    cudaGetSymbolAddress((void**)&w1h, g_w1h);
    cudaGetSymbolAddress((void**)&w1l, g_w1l);
    cudaGetSymbolAddress((void**)&w3h, g_w3h);
    cudaGetSymbolAddress((void**)&w3l, g_w3l);
    cudaGetSymbolAddress((void**)&y2,  g_y2);

    cudaFuncSetAttribute(dwconv_mma_kernel, cudaFuncAttributeMaxDynamicSharedMemorySize, DW_SMEM);
    cudaFuncSetAttribute(qkv_mma_kernel,    cudaFuncAttributeMaxDynamicSharedMemorySize, 131072);
    cudaFuncSetAttribute(proj_mma_kernel,   cudaFuncAttributeMaxDynamicSharedMemorySize, 131072);

    // 1. weight expansion + x convert
    expand_bf16_kernel<<<(OC1*IC1 + 255)/256, 256>>>(qkv_r, qkv_i, qkv_j, qkv_k, w1h, w1l, 96, 32, OC1*IC1);
    expand2_kernel<<<(9*OC2*IC2 + 255)/256, 256>>>(dw_r, dw_i, dw_j, dw_k);
    expand_bf16_kernel<<<(OC3*IC3 + 255)/256, 256>>>(po_r, po_i, po_j, po_k, w3h, w3l, 32, 32, OC3*IC3);
    convert_x_kernel<<<dim3(HW/32, IC1/32, BATCH), dim3(32, 8)>>>(x);

    // 2. qkv 1x1 conv (mma) -> y1 hi/lo [px][ic]
    qkv_mma_kernel<<<dim3(HW/128, OC1/128, BATCH), 256, 131072>>>(qkv_b);

    // 3. dw 3x3 conv (mma, window-reuse, N=256) -> y2 fp32
    dwconv_mma_kernel<<<dim3(HGT/2, OC2/128, BATCH), 256, DW_SMEM>>>(dw_b, y2);

    // 4-6. attention (norms fused into qk)
    qk_partial<<<dim3(32, 8), 256>>>();
    attn_softmax<<<8, 1024>>>(temp);
    av_kernel<<<dim3(HW/256, 8), 256>>>();

    // 7. projection (mma) -> d_out
    proj_mma_kernel<<<dim3(HW/128, 1, BATCH), 256, 131072>>>(po_b, out);
}